// round 7
// baseline (speedup 1.0000x reference)
#include <cuda_runtime.h>

#define HPX 512
#define WPX 512
#define HW  (HPX*WPX)           // 262144 = 2^18
#define HOB 518                 // r2 output side (512 + 2*4 - 2)
#define HW2 (HOB*HOB)           // 268324

typedef unsigned long long u64;

// ---------------- device scratch (no cudaMalloc allowed) ----------------
__device__ float g_t1raw[32*HW];
__device__ float g_t2raw[32*HW];
__device__ float g_graw [128*HW];
__device__ float g_r1raw[32*HW];
__device__ float g_r2raw[4*HW2];
__device__ __align__(16) float g_wt_e1[4*9*32];     // [z2][cin4][k9][16]
__device__ __align__(16) float g_wt_e2[32*9*32];    // [z2][cin32][k9][16]
__device__ __align__(16) float g_wt_g [4*64*9*32];  // [zz8][cin64][k9][16]
__device__ __align__(16) float g_wt_r1[32*9*32];    // [z2][cin32][k9][16]
__device__ __align__(16) float g_wt_r2[32*9*4];     // [cin32][k9][4]
__device__ float  g_stats[512];    // e1:[0,64) e2:[64,128) gates:[128,384) r1:[384,448) r2:[448,456)
__device__ float2 g_params[256];   // e1:0 e2:32 gates:64 r1:192 r2:224   (scale, bias)

// ---------------- f32x2 / cp.async helpers ----------------
__device__ __forceinline__ u64 pack2(float x) {
    unsigned u = __float_as_uint(x);
    u64 r;
    asm("mov.b64 %0, {%1, %2};" : "=l"(r) : "r"(u), "r"(u));
    return r;
}
__device__ __forceinline__ u64 ffma2(u64 a, u64 b, u64 c) {
    u64 d;
    asm("fma.rn.f32x2 %0, %1, %2, %3;" : "=l"(d) : "l"(a), "l"(b), "l"(c));
    return d;
}
__device__ __forceinline__ void unpack2(u64 v, float& lo, float& hi) {
    unsigned a, b;
    asm("mov.b64 {%0, %1}, %2;" : "=r"(a), "=r"(b) : "l"(v));
    lo = __uint_as_float(a); hi = __uint_as_float(b);
}
__device__ __forceinline__ float sigmoidf_(float x) { return 1.f / (1.f + expf(-x)); }

__device__ __forceinline__ void cp_async4(unsigned dst, const void* src, bool pred) {
    int bytes = pred ? 4 : 0;
    asm volatile("cp.async.ca.shared.global [%0], [%1], 4, %2;"
                 :: "r"(dst), "l"(src), "r"(bytes));
}
__device__ __forceinline__ void cp_async16(unsigned dst, const void* src) {
    asm volatile("cp.async.cg.shared.global [%0], [%1], 16;" :: "r"(dst), "l"(src));
}
__device__ __forceinline__ void cp_commit() {
    asm volatile("cp.async.commit_group;");
}
template<int N>
__device__ __forceinline__ void cp_wait() {
    asm volatile("cp.async.wait_group %0;" :: "n"(N));
}

// ---- weight prep: emit per-z-slice contiguous [z][cin][k][16] (+ stats zeroing) ----
__global__ void prep_weights(const float* __restrict__ we1, const float* __restrict__ we2,
                             const float* __restrict__ wf,  const float* __restrict__ wi,
                             const float* __restrict__ wc,  const float* __restrict__ wo,
                             const float* __restrict__ wr1, const float* __restrict__ wr2)
{
    int idx = blockIdx.x * 256 + threadIdx.x;
    if (idx < 512) g_stats[idx] = 0.f;
    // e1: [z2][cin4][k9][16] = 1152
    if (idx < 1152) {
        int cl = idx % 16, t = idx / 16, k = t % 9; t /= 9;
        int cin = t % 4, z = t / 4;
        g_wt_e1[idx] = we1[(z*16 + cl)*4*9 + cin*9 + k];
        return;
    }
    idx -= 1152;
    // e2: [z2][cin32][k9][16] = 9216
    if (idx < 9216) {
        int cl = idx % 16, t = idx / 16, k = t % 9; t /= 9;
        int cin = t % 32, z = t / 32;
        g_wt_e2[idx] = we2[(z*16 + cl)*32*9 + cin*9 + k];
        return;
    }
    idx -= 9216;
    // gates: [zz8][cin64][k9][16] = 73728 ; zz = gate*2 + half
    if (idx < 4*18432) {
        int cl = idx % 16, t = idx / 16, k = t % 9; t /= 9;
        int cin = t % 64, zz = t / 64;
        int g = zz >> 1, half = zz & 1;
        const float* src = (g == 0) ? wf : (g == 1) ? wi : (g == 2) ? wc : wo;
        g_wt_g[idx] = src[(half*16 + cl)*64*9 + cin*9 + k];
        return;
    }
    idx -= 4*18432;
    // r1: [z2][cin32][k9][16] = 9216
    if (idx < 9216) {
        int cl = idx % 16, t = idx / 16, k = t % 9; t /= 9;
        int cin = t % 32, z = t / 32;
        g_wt_r1[idx] = wr1[(z*16 + cl)*32*9 + cin*9 + k];
        return;
    }
    idx -= 9216;
    // r2: [cin32][k9][4], couts padded to 4
    if (idx < 1152) {
        int cout = idx % 4, t = idx / 4, k = t % 9, cin = t / 9;
        g_wt_r2[idx] = (cout < 3) ? wr2[cout*32*9 + cin*9 + k] : 0.f;
        return;
    }
}

// stats (sum, sumsq) -> params (scale, bias)
__global__ void make_params(const float* __restrict__ stats, float2* __restrict__ params,
                            int nch, float invn)
{
    int c = threadIdx.x;
    if (c >= nch) return;
    float m   = stats[2*c] * invn;
    float var = stats[2*c+1] * invn - m * m;
    float sc  = rsqrtf(var + 1e-5f);
    params[c] = make_float2(sc, -m * sc);
}

// ---------------- 3x3 conv v6: v5 pipeline, COUT z-sliced (COUTB per block) ------------------
// 256 threads = 2 groups x 128 (16x8). Output tile 32x8; thread -> px (tx, tx+16) at row ty
// for COUTB/2 output channels. blockIdx.z selects the cout slice (weights pre-sliced).
template<int CIN, int COUTB, int CHUNK>
__global__ void __launch_bounds__(256, 4)
conv3x3_v6(const float* __restrict__ inA, const float* __restrict__ inB, int csplit,
           const float2* __restrict__ prmA, const float2* __restrict__ prmB,
           int reluA, int reluB,
           const float* __restrict__ wt, float* __restrict__ out, float* __restrict__ statsOut,
           int H, int W, int pad, int HO, int WO)
{
    constexpr int TW = 32, TH = 8, TPW = 36, TPH = 10;   // halo 34x10, rows padded to 36
    constexpr int TSZ = TPW * TPH;                        // 360
    constexpr int NCH = CIN / CHUNK;
    constexpr int WCH = CHUNK * 9 * COUTB;                // weight floats per chunk
    constexpr int COUTG = COUTB / 2;
    constexpr int C2G = COUTG / 2;
    constexpr int C2  = COUTB / 2;
    extern __shared__ float smem[];
    float* ws   = smem;                                   // 2 * WCH
    float* tile = smem + 2*WCH;                           // 2 * CHUNK*TSZ
    __shared__ float sstat[2*COUTB];

    const int tid   = threadIdx.x;
    const int group = tid >> 7;
    const int tx    = tid & 15;
    const int ty    = (tid >> 4) & 7;
    if (tid < 2*COUTB) sstat[tid] = 0.f;

    const int gx = blockIdx.x * TW, gy = blockIdx.y * TH;
    const int oy = gy + ty;
    const int ox0 = gx + tx, ox1 = ox0 + 16;
    const float* wsrc = wt + (size_t)blockIdx.z * (CIN*9*COUTB);

    const unsigned ws_s   = (unsigned)__cvta_generic_to_shared(ws);
    const unsigned tile_s = (unsigned)__cvta_generic_to_shared(tile);
    const bool needT = (prmA != nullptr && csplit > 0) || (prmB != nullptr && csplit < CIN);

    u64 accA[C2G], accB[C2G];
#pragma unroll
    for (int p = 0; p < C2G; p++) { accA[p] = 0ull; accB[p] = 0ull; }

    auto prefetch = [&](int ci, int buf) {
        const float* wc = wsrc + (size_t)ci * WCH;
        unsigned wd = ws_s + buf * WCH * 4;
        for (int i = tid; i < WCH/4; i += 256)
            cp_async16(wd + i*16, wc + i*4);
        unsigned td = tile_s + buf * CHUNK*TSZ*4;
        for (int cc = 0; cc < CHUNK; ++cc) {
            int cin = ci*CHUNK + cc;
            bool isA = cin < csplit;
            const float* ip = isA ? (inA + (size_t)cin * H * W)
                                  : (inB + (size_t)(cin - csplit) * H * W);
            for (int i = tid; i < TSZ; i += 256) {
                int r = i / TPW, c = i % TPW;
                int iy = gy - pad + r, ix = gx - pad + c;
                bool inb = (c < TW+2) && iy >= 0 && iy < H && ix >= 0 && ix < W;
                cp_async4(td + (cc*TSZ + i)*4, inb ? (ip + (size_t)iy*W + ix) : ip, inb);
            }
        }
        cp_commit();
    };

    auto transform = [&](int ci, int buf) {
        float* tb = tile + buf * CHUNK*TSZ;
        for (int i = tid; i < CHUNK*TSZ; i += 256) {
            int cc = i / TSZ, e = i % TSZ;
            int cin = ci*CHUNK + cc;
            bool isA = cin < csplit;
            const float2* prm = isA ? prmA : prmB;
            if (!prm) continue;
            int rl = isA ? reluA : reluB;
            int r = e / TPW, c = e % TPW;
            int iy = gy - pad + r, ix = gx - pad + c;
            bool inb = (c < TW+2) && iy >= 0 && iy < H && ix >= 0 && ix < W;
            float2 p = __ldg(&prm[isA ? cin : (cin - csplit)]);
            float v = inb ? (tb[i] * p.x + p.y) : 0.f;
            if (rl) v = fmaxf(v, 0.f);
            tb[i] = v;
        }
    };

    auto compute = [&](int buf) {
        const float* tb0 = tile + buf * CHUNK*TSZ;
        const float* wsb = ws + buf * WCH;
#pragma unroll
        for (int cc = 0; cc < CHUNK; ++cc) {
            const float* tb = tb0 + cc * TSZ;
            float a[9], b[9];
#pragma unroll
            for (int ky = 0; ky < 3; ky++)
#pragma unroll
                for (int kx = 0; kx < 3; kx++) {
                    a[ky*3+kx] = tb[(ty + ky) * TPW + tx + kx];
                    b[ky*3+kx] = tb[(ty + ky) * TPW + tx + 16 + kx];
                }
            const u64* wrow = (const u64*)(wsb + cc * 9 * COUTB) + group * C2G;
#pragma unroll
            for (int k = 0; k < 9; k++) {
                u64 va = pack2(a[k]);
                u64 vb = pack2(b[k]);
                if constexpr (C2G >= 2) {
                    const ulonglong2* w4 = (const ulonglong2*)(wrow + (size_t)k * C2);
#pragma unroll
                    for (int p2 = 0; p2 < C2G/2; p2++) {
                        ulonglong2 w = w4[p2];
                        accA[2*p2  ] = ffma2(va, w.x, accA[2*p2  ]);
                        accB[2*p2  ] = ffma2(vb, w.x, accB[2*p2  ]);
                        accA[2*p2+1] = ffma2(va, w.y, accA[2*p2+1]);
                        accB[2*p2+1] = ffma2(vb, w.y, accB[2*p2+1]);
                    }
                } else {
                    u64 w = wrow[(size_t)k * C2];
                    accA[0] = ffma2(va, w, accA[0]);
                    accB[0] = ffma2(vb, w, accB[0]);
                }
            }
        }
    };

    prefetch(0, 0);
    for (int ci = 0; ci < NCH; ++ci) {
        int cur = ci & 1;
        if (ci + 1 < NCH) {
            prefetch(ci + 1, 1 - cur);
            cp_wait<1>();
        } else {
            cp_wait<0>();
        }
        __syncthreads();
        if (needT) { transform(ci, cur); __syncthreads(); }
        compute(cur);
        __syncthreads();
    }

    // ---- epilogue: store + fused per-channel (sum, sumsq) ----
    float* ob = out + (size_t)blockIdx.z * COUTB * HO * WO;
    float* so = statsOut + blockIdx.z * 2 * COUTB;
    const bool vA = (oy < HO) && (ox0 < WO);
    const bool vB = (oy < HO) && (ox1 < WO);
    const size_t row = (size_t)oy * WO;
#pragma unroll
    for (int p = 0; p < C2G; p++) {
        int c0 = group * COUTG + 2*p;
        float a0, a1, b0, b1;
        unpack2(accA[p], a0, a1);
        unpack2(accB[p], b0, b1);
        if (vA) {
            ob[(size_t)(c0  ) * HO * WO + row + ox0] = a0;
            ob[(size_t)(c0+1) * HO * WO + row + ox0] = a1;
        }
        if (vB) {
            ob[(size_t)(c0  ) * HO * WO + row + ox1] = b0;
            ob[(size_t)(c0+1) * HO * WO + row + ox1] = b1;
        }
        float s0 = (vA ? a0 : 0.f) + (vB ? b0 : 0.f);
        float q0 = (vA ? a0*a0 : 0.f) + (vB ? b0*b0 : 0.f);
        float s1 = (vA ? a1 : 0.f) + (vB ? b1 : 0.f);
        float q1 = (vA ? a1*a1 : 0.f) + (vB ? b1*b1 : 0.f);
#pragma unroll
        for (int o = 16; o; o >>= 1) {
            s0 += __shfl_down_sync(0xFFFFFFFFu, s0, o);
            q0 += __shfl_down_sync(0xFFFFFFFFu, q0, o);
            s1 += __shfl_down_sync(0xFFFFFFFFu, s1, o);
            q1 += __shfl_down_sync(0xFFFFFFFFu, q1, o);
        }
        if ((tid & 31) == 0) {
            atomicAdd(&sstat[2*c0  ], s0);
            atomicAdd(&sstat[2*c0+1], q0);
            atomicAdd(&sstat[2*c0+2], s1);
            atomicAdd(&sstat[2*c0+3], q1);
        }
    }
    __syncthreads();
    if (tid < 2*COUTB) atomicAdd(&so[tid], sstat[tid]);
}

// ---------------- LSTM elementwise ----------------
__global__ void lstm_kernel(const float* __restrict__ prev_c, const float2* __restrict__ prm,
                            float* __restrict__ out_c, float* __restrict__ out_h)
{
    int idx = blockIdx.x * 256 + threadIdx.x;   // over 32*HW
    int c = idx >> 18;                          // HW = 2^18
    const int CHW = 32 * HW;

    float g[4];
#pragma unroll
    for (int gi = 0; gi < 4; gi++) {
        float2 p = prm[gi*32 + c];
        g[gi] = g_graw[(size_t)gi * CHW + idx] * p.x + p.y;
    }
    float f  = sigmoidf_(g[0]);
    float it = sigmoidf_(g[1]);
    float ct = tanhf(g[2]);
    float ot = sigmoidf_(g[3]);
    float nc = prev_c[idx] * f + it * ct;
    out_c[idx] = nc;
    out_h[idx] = tanhf(nc) * ot;
}

// ---------------- patch gather + per-channel dot ----------------
__global__ void gather_kernel(const int* __restrict__ holes,
                              const float* __restrict__ woil, const float* __restrict__ boil,
                              const float* __restrict__ wwat, const float* __restrict__ bwat,
                              const float* __restrict__ wgas, const float* __restrict__ bgas,
                              const float2* __restrict__ prm,
                              float* __restrict__ res)
{
    int nidx = threadIdx.x;
    if (nidx >= 256) return;
    int hx = holes[2*nidx], hy = holes[2*nidx+1];
    const float* wv[3] = { woil, wwat, wgas };
    float bv[3] = { boil[0], bwat[0], bgas[0] };
    for (int c = 0; c < 3; c++) {
        float2 p = prm[c];
        float s = bv[c];
        for (int i = 0; i < 3; i++)
            for (int j = 0; j < 3; j++) {
                float v = g_r2raw[(size_t)c * HW2 + (size_t)(hx + 3 + i) * HOB + (hy + 3 + j)];
                s += wv[c][i*3+j] * (v * p.x + p.y);
            }
        res[nidx*3 + c] = s;
    }
}

// ---------------- launch ----------------
extern "C" void kernel_launch(void* const* d_in, const int* in_sizes, int n_in,
                              void* d_out, int out_size)
{
    const float* x      = (const float*)d_in[0];
    const float* prev_c = (const float*)d_in[1];
    const float* prev_h = (const float*)d_in[2];
    const int*   holes  = (const int*)d_in[3];
    const float* w_e1   = (const float*)d_in[4];
    const float* w_e2   = (const float*)d_in[5];
    const float* w_f    = (const float*)d_in[6];
    const float* w_i    = (const float*)d_in[7];
    const float* w_c    = (const float*)d_in[8];
    const float* w_o    = (const float*)d_in[9];
    const float* w_r1   = (const float*)d_in[10];
    const float* w_r2   = (const float*)d_in[11];
    const float* w_oil  = (const float*)d_in[12];
    const float* b_oil  = (const float*)d_in[13];
    const float* w_wat  = (const float*)d_in[14];
    const float* b_wat  = (const float*)d_in[15];
    const float* w_gas  = (const float*)d_in[16];
    const float* b_gas  = (const float*)d_in[17];
    float* out = (float*)d_out;

    float *t1raw, *t2raw, *graw, *r1raw, *r2raw;
    float *wt_e1, *wt_e2, *wt_g, *wt_r1, *wt_r2, *stats;
    float2 *params;
    cudaGetSymbolAddress((void**)&t1raw, g_t1raw);
    cudaGetSymbolAddress((void**)&t2raw, g_t2raw);
    cudaGetSymbolAddress((void**)&graw,  g_graw);
    cudaGetSymbolAddress((void**)&r1raw, g_r1raw);
    cudaGetSymbolAddress((void**)&r2raw, g_r2raw);
    cudaGetSymbolAddress((void**)&wt_e1, g_wt_e1);
    cudaGetSymbolAddress((void**)&wt_e2, g_wt_e2);
    cudaGetSymbolAddress((void**)&wt_g,  g_wt_g);
    cudaGetSymbolAddress((void**)&wt_r1, g_wt_r1);
    cudaGetSymbolAddress((void**)&wt_r2, g_wt_r2);
    cudaGetSymbolAddress((void**)&stats, g_stats);
    cudaGetSymbolAddress((void**)&params, g_params);

    constexpr int TSZ = 36 * 10;
    const int SM_E1 = (2*4*9*16 + 2*4*TSZ) * 4;     // 16128
    const int SM_16 = (2*8*9*16 + 2*8*TSZ) * 4;     // 32256
    const int SM_R2 = (2*8*9*4  + 2*8*TSZ) * 4;     // 25344
    cudaFuncSetAttribute((const void*)conv3x3_v6<4,16,4>,  cudaFuncAttributeMaxDynamicSharedMemorySize, SM_E1);
    cudaFuncSetAttribute((const void*)conv3x3_v6<32,16,8>, cudaFuncAttributeMaxDynamicSharedMemorySize, SM_16);
    cudaFuncSetAttribute((const void*)conv3x3_v6<64,16,8>, cudaFuncAttributeMaxDynamicSharedMemorySize, SM_16);
    cudaFuncSetAttribute((const void*)conv3x3_v6<32,4,8>,  cudaFuncAttributeMaxDynamicSharedMemorySize, SM_R2);

    dim3 thr(256);
    dim3 grid512(512/32, 512/8, 2);        // 16 x 64 x 2  (two 16-cout slices)
    dim3 gridG  (512/32, 512/8, 8);        // 4 gates x 2 halves
    dim3 gridR2 ((HOB + 31)/32, (HOB + 7)/8, 1);   // 17 x 65

    // launch order arranged so the 6th launch (ncu -s 5 -c 1) is the gates conv
    prep_weights<<<(94464 + 255)/256, 256>>>(w_e1, w_e2, w_f, w_i, w_c, w_o, w_r1, w_r2);

    // e1: x (4ch, raw) -> t1raw (+stats)
    conv3x3_v6<4,16,4><<<grid512, thr, SM_E1>>>(x, x, 4, nullptr, nullptr, 0, 0,
                                                wt_e1, t1raw, stats + 0, 512, 512, 1, 512, 512);
    make_params<<<1, 32>>>(stats + 0, params + 0, 32, 1.f / (float)HW);

    // e2: relu(BN(t1raw)) -> t2raw (+stats)
    conv3x3_v6<32,16,8><<<grid512, thr, SM_16>>>(t1raw, t1raw, 32, params + 0, params + 0, 1, 1,
                                                 wt_e2, t2raw, stats + 64, 512, 512, 1, 512, 512);
    make_params<<<1, 32>>>(stats + 64, params + 32, 32, 1.f / (float)HW);

    // gates: [prev_h (raw) ; BN(t2raw)] -> graw (8 x 16ch over z) (+stats)  [profiled launch]
    conv3x3_v6<64,16,8><<<gridG, thr, SM_16>>>(prev_h, t2raw, 32, nullptr, params + 32, 0, 0,
                                               wt_g, graw, stats + 128, 512, 512, 1, 512, 512);
    make_params<<<1, 128>>>(stats + 128, params + 64, 128, 1.f / (float)HW);

    // LSTM -> out[0:32HW]=next_c, out[32HW:64HW]=next_h
    lstm_kernel<<<32*HW/256, 256>>>(prev_c, params + 64, out, out + 32*HW);

    // r1: next_h (raw) -> r1raw (+stats)
    conv3x3_v6<32,16,8><<<grid512, thr, SM_16>>>(out + 32*HW, out + 32*HW, 32, nullptr, nullptr, 0, 0,
                                                 wt_r1, r1raw, stats + 384, 512, 512, 1, 512, 512);
    make_params<<<1, 32>>>(stats + 384, params + 192, 32, 1.f / (float)HW);

    // r2: relu(BN(r1raw)) -> r2raw (3+1 ch @ 518x518, pad 4) (+stats)
    conv3x3_v6<32,4,8><<<gridR2, thr, SM_R2>>>(r1raw, r1raw, 32, params + 192, params + 192, 1, 1,
                                               wt_r2, r2raw, stats + 448, 512, 512, 4, HOB, HOB);
    make_params<<<1, 32>>>(stats + 448, params + 224, 4, 1.f / (float)HW2);

    // gather + dot -> out tail
    gather_kernel<<<1, 256>>>(holes, w_oil, b_oil, w_wat, b_wat, w_gas, b_gas, params + 224, out + 64*HW);
}

// round 9
// speedup vs baseline: 1.4851x; 1.4851x over previous
#include <cuda_runtime.h>

#define HPX 512
#define WPX 512
#define HW  (HPX*WPX)           // 262144 = 2^18
#define HOB 518                 // r2 output side (512 + 2*4 - 2)
#define HW2 (HOB*HOB)           // 268324

typedef unsigned long long u64;

// ---------------- device scratch (no cudaMalloc allowed) ----------------
__device__ float g_t1raw[32*HW];
__device__ float g_t2raw[32*HW];
__device__ float g_graw [128*HW];
__device__ float g_r1raw[32*HW];
__device__ float g_r2raw[4*HW2];
__device__ __align__(16) float g_wt_e1[4*9*32];
__device__ __align__(16) float g_wt_e2[32*9*32];
__device__ __align__(16) float g_wt_g [4*64*9*32];
__device__ __align__(16) float g_wt_r1[32*9*32];
__device__ __align__(16) float g_wt_r2[32*9*4];
__device__ float  g_stats[512];    // e1:[0,64) e2:[64,128) gates:[128,384) r1:[384,448) r2:[448,456)
__device__ float2 g_params[256];   // e1:0 e2:32 gates:64 r1:192 r2:224   (scale, bias)

// ---------------- f32x2 / cp.async helpers ----------------
__device__ __forceinline__ u64 pack2(float x) {
    unsigned u = __float_as_uint(x);
    u64 r;
    asm("mov.b64 %0, {%1, %2};" : "=l"(r) : "r"(u), "r"(u));
    return r;
}
__device__ __forceinline__ u64 ffma2(u64 a, u64 b, u64 c) {
    u64 d;
    asm("fma.rn.f32x2 %0, %1, %2, %3;" : "=l"(d) : "l"(a), "l"(b), "l"(c));
    return d;
}
__device__ __forceinline__ void unpack2(u64 v, float& lo, float& hi) {
    unsigned a, b;
    asm("mov.b64 {%0, %1}, %2;" : "=r"(a), "=r"(b) : "l"(v));
    lo = __uint_as_float(a); hi = __uint_as_float(b);
}
__device__ __forceinline__ float sigmoidf_(float x) { return 1.f / (1.f + expf(-x)); }

__device__ __forceinline__ void cp_async4(unsigned dst, const void* src, bool pred) {
    int bytes = pred ? 4 : 0;
    asm volatile("cp.async.ca.shared.global [%0], [%1], 4, %2;"
                 :: "r"(dst), "l"(src), "r"(bytes));
}
__device__ __forceinline__ void cp_async16(unsigned dst, const void* src) {
    asm volatile("cp.async.cg.shared.global [%0], [%1], 16;" :: "r"(dst), "l"(src));
}
__device__ __forceinline__ void cp_commit() {
    asm volatile("cp.async.commit_group;");
}
template<int N>
__device__ __forceinline__ void cp_wait() {
    asm volatile("cp.async.wait_group %0;" :: "n"(N));
}

// ---------------- weight transpose/prep (+ stats zeroing): [cout][cin][k] -> [cin*9+k][cout] --
__global__ void prep_weights(const float* __restrict__ we1, const float* __restrict__ we2,
                             const float* __restrict__ wf,  const float* __restrict__ wi,
                             const float* __restrict__ wc,  const float* __restrict__ wo,
                             const float* __restrict__ wr1, const float* __restrict__ wr2)
{
    int idx = blockIdx.x * 256 + threadIdx.x;
    if (idx < 512) g_stats[idx] = 0.f;
    if (idx < 1152) {
        int cout = idx % 32, t = idx / 32, k = t % 9, cin = t / 9;
        g_wt_e1[idx] = we1[cout*4*9 + cin*9 + k];
        return;
    }
    idx -= 1152;
    if (idx < 9216) {
        int cout = idx % 32, t = idx / 32, k = t % 9, cin = t / 9;
        g_wt_e2[idx] = we2[cout*32*9 + cin*9 + k];
        return;
    }
    idx -= 9216;
    if (idx < 4*18432) {
        int g = idx / 18432, d = idx % 18432;
        int cout = d % 32, t = d / 32, k = t % 9, cin = t / 9;
        const float* src = (g == 0) ? wf : (g == 1) ? wi : (g == 2) ? wc : wo;
        g_wt_g[idx] = src[cout*64*9 + cin*9 + k];
        return;
    }
    idx -= 4*18432;
    if (idx < 9216) {
        int cout = idx % 32, t = idx / 32, k = t % 9, cin = t / 9;
        g_wt_r1[idx] = wr1[cout*32*9 + cin*9 + k];
        return;
    }
    idx -= 9216;
    if (idx < 1152) {
        int cout = idx % 4, t = idx / 4, k = t % 9, cin = t / 9;
        g_wt_r2[idx] = (cout < 3) ? wr2[cout*32*9 + cin*9 + k] : 0.f;
        return;
    }
}

// stats (sum, sumsq) -> params (scale, bias)
__global__ void make_params(const float* __restrict__ stats, float2* __restrict__ params,
                            int nch, float invn)
{
    int c = threadIdx.x;
    if (c >= nch) return;
    float m   = stats[2*c] * invn;
    float var = stats[2*c+1] * invn - m * m;
    float sc  = rsqrtf(var + 1e-5f);
    params[c] = make_float2(sc, -m * sc);
}

// ---------------- 3x3 conv v8: v5 pipeline + k-outer compute + 4 CTAs/SM ---------------------
// 256 threads = 2 groups x 128 (16x8). Output tile 32x8; thread -> px (tx, tx+16) at row ty
// for COUT/2 output channels. cp.async double-buffered chunks; BN via in-smem transform pass.
template<int CIN, int COUT, int CHUNK>
__global__ void __launch_bounds__(256, 4)
conv3x3_v8(const float* __restrict__ inA, const float* __restrict__ inB, int csplit,
           const float2* __restrict__ prmA, const float2* __restrict__ prmB,
           int reluA, int reluB,
           const float* __restrict__ wt, float* __restrict__ out, float* __restrict__ statsOut,
           int H, int W, int pad, int HO, int WO)
{
    constexpr int TW = 32, TH = 8, TPW = 36, TPH = 10;   // halo 34x10, rows padded to 36
    constexpr int TSZ = TPW * TPH;                        // 360
    constexpr int NCH = CIN / CHUNK;
    constexpr int WCH = CHUNK * 9 * COUT;
    constexpr int COUTG = COUT / 2;
    constexpr int C2G = COUTG / 2;
    constexpr int C2  = COUT / 2;
    extern __shared__ float smem[];
    float* ws   = smem;                                   // 2 * WCH
    float* tile = smem + 2*WCH;                           // 2 * CHUNK*TSZ
    __shared__ float sstat[2*COUT];

    const int tid   = threadIdx.x;
    const int group = tid >> 7;
    const int tx    = tid & 15;
    const int ty    = (tid >> 4) & 7;
    if (tid < 2*COUT) sstat[tid] = 0.f;

    const int gx = blockIdx.x * TW, gy = blockIdx.y * TH;
    const int oy = gy + ty;
    const int ox0 = gx + tx, ox1 = ox0 + 16;
    const float* wsrc = wt + (size_t)blockIdx.z * (CIN*9*COUT);

    const unsigned ws_s   = (unsigned)__cvta_generic_to_shared(ws);
    const unsigned tile_s = (unsigned)__cvta_generic_to_shared(tile);
    const bool needT = (prmA != nullptr && csplit > 0) || (prmB != nullptr && csplit < CIN);

    u64 accA[C2G], accB[C2G];
#pragma unroll
    for (int p = 0; p < C2G; p++) { accA[p] = 0ull; accB[p] = 0ull; }

    auto prefetch = [&](int ci, int buf) {
        const float* wc = wsrc + (size_t)ci * WCH;
        unsigned wd = ws_s + buf * WCH * 4;
        for (int i = tid; i < WCH/4; i += 256)
            cp_async16(wd + i*16, wc + i*4);
        unsigned td = tile_s + buf * CHUNK*TSZ*4;
        for (int cc = 0; cc < CHUNK; ++cc) {
            int cin = ci*CHUNK + cc;
            bool isA = cin < csplit;
            const float* ip = isA ? (inA + (size_t)cin * H * W)
                                  : (inB + (size_t)(cin - csplit) * H * W);
            for (int i = tid; i < TSZ; i += 256) {
                int r = i / TPW, c = i % TPW;
                int iy = gy - pad + r, ix = gx - pad + c;
                bool inb = (c < TW+2) && iy >= 0 && iy < H && ix >= 0 && ix < W;
                cp_async4(td + (cc*TSZ + i)*4, inb ? (ip + (size_t)iy*W + ix) : ip, inb);
            }
        }
        cp_commit();
    };

    auto transform = [&](int ci, int buf) {
        float* tb = tile + buf * CHUNK*TSZ;
        for (int i = tid; i < CHUNK*TSZ; i += 256) {
            int cc = i / TSZ, e = i % TSZ;
            int cin = ci*CHUNK + cc;
            bool isA = cin < csplit;
            const float2* prm = isA ? prmA : prmB;
            if (!prm) continue;
            int rl = isA ? reluA : reluB;
            int r = e / TPW, c = e % TPW;
            int iy = gy - pad + r, ix = gx - pad + c;
            bool inb = (c < TW+2) && iy >= 0 && iy < H && ix >= 0 && ix < W;
            float2 p = __ldg(&prm[isA ? cin : (cin - csplit)]);
            float v = inb ? (tb[i] * p.x + p.y) : 0.f;
            if (rl) v = fmaxf(v, 0.f);
            tb[i] = v;
        }
    };

    // k-outer compute: minimal live state (2 packed pixels + current weight vectors)
    auto compute = [&](int buf) {
        const float* tb0 = tile + buf * CHUNK*TSZ + ty * TPW + tx;
        const float* wsb = ws + buf * WCH;
#pragma unroll
        for (int cc = 0; cc < CHUNK; ++cc) {
            const float* tb = tb0 + cc * TSZ;
            const u64* wrow = (const u64*)(wsb + cc * 9 * COUT) + group * C2G;
#pragma unroll
            for (int ky = 0; ky < 3; ky++) {
#pragma unroll
                for (int kx = 0; kx < 3; kx++) {
                    u64 va = pack2(tb[ky*TPW + kx]);
                    u64 vb = pack2(tb[ky*TPW + kx + 16]);
                    if constexpr (C2G >= 2) {
                        const ulonglong2* w4 = (const ulonglong2*)(wrow + (ky*3+kx) * C2);
#pragma unroll
                        for (int p2 = 0; p2 < C2G/2; p2++) {
                            ulonglong2 w = w4[p2];
                            accA[2*p2  ] = ffma2(va, w.x, accA[2*p2  ]);
                            accB[2*p2  ] = ffma2(vb, w.x, accB[2*p2  ]);
                            accA[2*p2+1] = ffma2(va, w.y, accA[2*p2+1]);
                            accB[2*p2+1] = ffma2(vb, w.y, accB[2*p2+1]);
                        }
                    } else {
                        u64 w = wrow[(ky*3+kx) * C2];
                        accA[0] = ffma2(va, w, accA[0]);
                        accB[0] = ffma2(vb, w, accB[0]);
                    }
                }
            }
        }
    };

    prefetch(0, 0);
    for (int ci = 0; ci < NCH; ++ci) {
        int cur = ci & 1;
        if (ci + 1 < NCH) {
            prefetch(ci + 1, 1 - cur);
            cp_wait<1>();
        } else {
            cp_wait<0>();
        }
        __syncthreads();
        if (needT) { transform(ci, cur); __syncthreads(); }
        compute(cur);
        __syncthreads();
    }

    // ---- epilogue: store + fused per-channel (sum, sumsq) ----
    float* ob = out + (size_t)blockIdx.z * COUT * HO * WO;
    float* so = statsOut + blockIdx.z * 2 * COUT;
    const bool vA = (oy < HO) && (ox0 < WO);
    const bool vB = (oy < HO) && (ox1 < WO);
    const size_t row = (size_t)oy * WO;
#pragma unroll
    for (int p = 0; p < C2G; p++) {
        int c0 = group * COUTG + 2*p;
        float a0, a1, b0, b1;
        unpack2(accA[p], a0, a1);
        unpack2(accB[p], b0, b1);
        if (vA) {
            ob[(size_t)(c0  ) * HO * WO + row + ox0] = a0;
            ob[(size_t)(c0+1) * HO * WO + row + ox0] = a1;
        }
        if (vB) {
            ob[(size_t)(c0  ) * HO * WO + row + ox1] = b0;
            ob[(size_t)(c0+1) * HO * WO + row + ox1] = b1;
        }
        float s0 = (vA ? a0 : 0.f) + (vB ? b0 : 0.f);
        float q0 = (vA ? a0*a0 : 0.f) + (vB ? b0*b0 : 0.f);
        float s1 = (vA ? a1 : 0.f) + (vB ? b1 : 0.f);
        float q1 = (vA ? a1*a1 : 0.f) + (vB ? b1*b1 : 0.f);
#pragma unroll
        for (int o = 16; o; o >>= 1) {
            s0 += __shfl_down_sync(0xFFFFFFFFu, s0, o);
            q0 += __shfl_down_sync(0xFFFFFFFFu, q0, o);
            s1 += __shfl_down_sync(0xFFFFFFFFu, s1, o);
            q1 += __shfl_down_sync(0xFFFFFFFFu, q1, o);
        }
        if ((tid & 31) == 0) {
            atomicAdd(&sstat[2*c0  ], s0);
            atomicAdd(&sstat[2*c0+1], q0);
            atomicAdd(&sstat[2*c0+2], s1);
            atomicAdd(&sstat[2*c0+3], q1);
        }
    }
    __syncthreads();
    if (tid < 2*COUT) atomicAdd(&so[tid], sstat[tid]);
}

// ---------------- LSTM elementwise ----------------
__global__ void lstm_kernel(const float* __restrict__ prev_c, const float2* __restrict__ prm,
                            float* __restrict__ out_c, float* __restrict__ out_h)
{
    int idx = blockIdx.x * 256 + threadIdx.x;   // over 32*HW
    int c = idx >> 18;                          // HW = 2^18
    const int CHW = 32 * HW;

    float g[4];
#pragma unroll
    for (int gi = 0; gi < 4; gi++) {
        float2 p = prm[gi*32 + c];
        g[gi] = g_graw[(size_t)gi * CHW + idx] * p.x + p.y;
    }
    float f  = sigmoidf_(g[0]);
    float it = sigmoidf_(g[1]);
    float ct = tanhf(g[2]);
    float ot = sigmoidf_(g[3]);
    float nc = prev_c[idx] * f + it * ct;
    out_c[idx] = nc;
    out_h[idx] = tanhf(nc) * ot;
}

// ---------------- patch gather + per-channel dot ----------------
__global__ void gather_kernel(const int* __restrict__ holes,
                              const float* __restrict__ woil, const float* __restrict__ boil,
                              const float* __restrict__ wwat, const float* __restrict__ bwat,
                              const float* __restrict__ wgas, const float* __restrict__ bgas,
                              const float2* __restrict__ prm,
                              float* __restrict__ res)
{
    int nidx = threadIdx.x;
    if (nidx >= 256) return;
    int hx = holes[2*nidx], hy = holes[2*nidx+1];
    const float* wv[3] = { woil, wwat, wgas };
    float bv[3] = { boil[0], bwat[0], bgas[0] };
    for (int c = 0; c < 3; c++) {
        float2 p = prm[c];
        float s = bv[c];
        for (int i = 0; i < 3; i++)
            for (int j = 0; j < 3; j++) {
                float v = g_r2raw[(size_t)c * HW2 + (size_t)(hx + 3 + i) * HOB + (hy + 3 + j)];
                s += wv[c][i*3+j] * (v * p.x + p.y);
            }
        res[nidx*3 + c] = s;
    }
}

// ---------------- launch ----------------
extern "C" void kernel_launch(void* const* d_in, const int* in_sizes, int n_in,
                              void* d_out, int out_size)
{
    const float* x      = (const float*)d_in[0];
    const float* prev_c = (const float*)d_in[1];
    const float* prev_h = (const float*)d_in[2];
    const int*   holes  = (const int*)d_in[3];
    const float* w_e1   = (const float*)d_in[4];
    const float* w_e2   = (const float*)d_in[5];
    const float* w_f    = (const float*)d_in[6];
    const float* w_i    = (const float*)d_in[7];
    const float* w_c    = (const float*)d_in[8];
    const float* w_o    = (const float*)d_in[9];
    const float* w_r1   = (const float*)d_in[10];
    const float* w_r2   = (const float*)d_in[11];
    const float* w_oil  = (const float*)d_in[12];
    const float* b_oil  = (const float*)d_in[13];
    const float* w_wat  = (const float*)d_in[14];
    const float* b_wat  = (const float*)d_in[15];
    const float* w_gas  = (const float*)d_in[16];
    const float* b_gas  = (const float*)d_in[17];
    float* out = (float*)d_out;

    float *t1raw, *t2raw, *graw, *r1raw, *r2raw;
    float *wt_e1, *wt_e2, *wt_g, *wt_r1, *wt_r2, *stats;
    float2 *params;
    cudaGetSymbolAddress((void**)&t1raw, g_t1raw);
    cudaGetSymbolAddress((void**)&t2raw, g_t2raw);
    cudaGetSymbolAddress((void**)&graw,  g_graw);
    cudaGetSymbolAddress((void**)&r1raw, g_r1raw);
    cudaGetSymbolAddress((void**)&r2raw, g_r2raw);
    cudaGetSymbolAddress((void**)&wt_e1, g_wt_e1);
    cudaGetSymbolAddress((void**)&wt_e2, g_wt_e2);
    cudaGetSymbolAddress((void**)&wt_g,  g_wt_g);
    cudaGetSymbolAddress((void**)&wt_r1, g_wt_r1);
    cudaGetSymbolAddress((void**)&wt_r2, g_wt_r2);
    cudaGetSymbolAddress((void**)&stats, g_stats);
    cudaGetSymbolAddress((void**)&params, g_params);

    constexpr int TSZ = 36 * 10;
    const int SM_E1 = (2*4*9*32  + 2*4*TSZ) * 4;    // 20736
    const int SM_32 = (2*8*9*32  + 2*8*TSZ) * 4;    // 41472
    const int SM_R2 = (2*8*9*4   + 2*8*TSZ) * 4;    // 25344
    cudaFuncSetAttribute((const void*)conv3x3_v8<4,32,4>,  cudaFuncAttributeMaxDynamicSharedMemorySize, SM_E1);
    cudaFuncSetAttribute((const void*)conv3x3_v8<32,32,8>, cudaFuncAttributeMaxDynamicSharedMemorySize, SM_32);
    cudaFuncSetAttribute((const void*)conv3x3_v8<64,32,8>, cudaFuncAttributeMaxDynamicSharedMemorySize, SM_32);
    cudaFuncSetAttribute((const void*)conv3x3_v8<32,4,8>,  cudaFuncAttributeMaxDynamicSharedMemorySize, SM_R2);

    dim3 thr(256);
    dim3 grid512(512/32, 512/8, 1);        // 16 x 64
    dim3 gridG  (512/32, 512/8, 4);
    dim3 gridR2 ((HOB + 31)/32, (HOB + 7)/8, 1);   // 17 x 65

    // launch order arranged so the 6th launch (ncu -s 5 -c 1) is the gates conv
    prep_weights<<<(94464 + 255)/256, 256>>>(w_e1, w_e2, w_f, w_i, w_c, w_o, w_r1, w_r2);

    // e1: x (4ch, raw) -> t1raw (+stats)
    conv3x3_v8<4,32,4><<<grid512, thr, SM_E1>>>(x, x, 4, nullptr, nullptr, 0, 0,
                                                wt_e1, t1raw, stats + 0, 512, 512, 1, 512, 512);
    make_params<<<1, 32>>>(stats + 0, params + 0, 32, 1.f / (float)HW);

    // e2: relu(BN(t1raw)) -> t2raw (+stats)
    conv3x3_v8<32,32,8><<<grid512, thr, SM_32>>>(t1raw, t1raw, 32, params + 0, params + 0, 1, 1,
                                                 wt_e2, t2raw, stats + 64, 512, 512, 1, 512, 512);
    make_params<<<1, 32>>>(stats + 64, params + 32, 32, 1.f / (float)HW);

    // gates: [prev_h (raw) ; BN(t2raw)] -> graw (4 x 32ch over z) (+stats)  [profiled launch]
    conv3x3_v8<64,32,8><<<gridG, thr, SM_32>>>(prev_h, t2raw, 32, nullptr, params + 32, 0, 0,
                                               wt_g, graw, stats + 128, 512, 512, 1, 512, 512);
    make_params<<<1, 128>>>(stats + 128, params + 64, 128, 1.f / (float)HW);

    // LSTM -> out[0:32HW]=next_c, out[32HW:64HW]=next_h
    lstm_kernel<<<32*HW/256, 256>>>(prev_c, params + 64, out, out + 32*HW);

    // r1: next_h (raw) -> r1raw (+stats)
    conv3x3_v8<32,32,8><<<grid512, thr, SM_32>>>(out + 32*HW, out + 32*HW, 32, nullptr, nullptr, 0, 0,
                                                 wt_r1, r1raw, stats + 384, 512, 512, 1, 512, 512);
    make_params<<<1, 32>>>(stats + 384, params + 192, 32, 1.f / (float)HW);

    // r2: relu(BN(r1raw)) -> r2raw (3+1 ch @ 518x518, pad 4) (+stats)
    conv3x3_v8<32,4,8><<<gridR2, thr, SM_R2>>>(r1raw, r1raw, 32, params + 192, params + 192, 1, 1,
                                               wt_r2, r2raw, stats + 448, 512, 512, 4, HOB, HOB);
    make_params<<<1, 32>>>(stats + 448, params + 224, 4, 1.f / (float)HW2);

    // gather + dot -> out tail
    gather_kernel<<<1, 256>>>(holes, w_oil, b_oil, w_wat, b_wat, w_gas, b_gas, params + 224, out + 64*HW);
}